// round 16
// baseline (speedup 1.0000x reference)
#include <cuda_runtime.h>
#include <cstdint>
#include <math.h>

#define HID 512
#define NH 8
#define MAXN 100000
#define EPS 1e-5f

// ---------------- scratch (device globals) ---------------------------------
__device__ uint32_t g_x_bf[(size_t)MAXN * 256];    // x bf16 [n][512]
__device__ uint32_t g_fx_bf[(size_t)MAXN * 256];   // fx bf16 [n][512]
__device__ uint32_t g_w_bf[(size_t)MAXN * 256];    // softmax w bf16 [n][512]
__device__ uint32_t g_Wls_bf[512 * 256];           // folded logits W bf16 [hg][512]
__device__ uint32_t g_Wfx_bf[512 * 256];           // Wfx bf16
__device__ uint32_t g_P_bf[512 * 256];             // folded unpool+outproj bf16 [o][hg]
__device__ float g_bls[512];
__device__ float g_tokens[NH * 64 * 64];
__device__ float g_norm[NH * 64];
__device__ float g_ot[NH * 64 * 64];               // out_tok (attn output)

// ---------------- helpers ---------------------------------------------------
__device__ __forceinline__ uint32_t smem_u32(const void* p) {
    uint32_t a;
    asm("{ .reg .u64 t; cvta.to.shared.u64 t, %1; cvt.u32.u64 %0, t; }" : "=r"(a) : "l"(p));
    return a;
}
__device__ __forceinline__ uint32_t pk(float lo, float hi) {
    uint32_t r;
    asm("cvt.rn.bf16x2.f32 %0, %1, %2;" : "=r"(r) : "f"(hi), "f"(lo));
    return r;
}
__device__ __forceinline__ void cp_async16(uint32_t dst, const void* src, int sz) {
    asm volatile("cp.async.ca.shared.global [%0], [%1], 16, %2;"
                 :: "r"(dst), "l"(src), "r"(sz));
}
__device__ __forceinline__ void cp_commit() {
    asm volatile("cp.async.commit_group;" ::: "memory");
}
template <int N>
__device__ __forceinline__ void cp_wait() {
    asm volatile("cp.async.wait_group %0;" :: "n"(N) : "memory");
}
__device__ __forceinline__ void mma_bf16(float* c, uint32_t a0, uint32_t a1,
                                         uint32_t a2, uint32_t a3,
                                         uint32_t b0, uint32_t b1) {
    asm volatile(
        "mma.sync.aligned.m16n8k16.row.col.f32.bf16.bf16.f32 "
        "{%0,%1,%2,%3}, {%4,%5,%6,%7}, {%8,%9}, {%0,%1,%2,%3};"
        : "+f"(c[0]), "+f"(c[1]), "+f"(c[2]), "+f"(c[3])
        : "r"(a0), "r"(a1), "r"(a2), "r"(a3), "r"(b0), "r"(b1));
}
__device__ __forceinline__ void ldm_x4(uint32_t* r, uint32_t addr) {
    asm volatile("ldmatrix.sync.aligned.m8n8.x4.shared.b16 {%0,%1,%2,%3}, [%4];"
                 : "=r"(r[0]), "=r"(r[1]), "=r"(r[2]), "=r"(r[3]) : "r"(addr));
}
__device__ __forceinline__ void ldm_x4t(uint32_t* r, uint32_t addr) {
    asm volatile("ldmatrix.sync.aligned.m8n8.x4.trans.shared.b16 {%0,%1,%2,%3}, [%4];"
                 : "=r"(r[0]), "=r"(r[1]), "=r"(r[2]), "=r"(r[3]) : "r"(addr));
}
__device__ __forceinline__ void ldm_x2t(uint32_t& r0, uint32_t& r1, uint32_t addr) {
    asm volatile("ldmatrix.sync.aligned.m8n8.x2.trans.shared.b16 {%0,%1}, [%2];"
                 : "=r"(r0), "=r"(r1) : "r"(addr));
}

// ---------------------------------------------------------------------------
// k_pre: fused prelude. Blocks [0, preBlocks) do zero + x->bf16 + Wfx->bf16;
// blocks [preBlocks, preBlocks+256) do prep1 (Wls fold), overlapping with the
// HBM-bound conversion blocks.
#define WFX_QUADS 65536

__global__ __launch_bounds__(256) void k_pre(
    const float* __restrict__ x, const float* __restrict__ Wfx,
    const float* __restrict__ Wx, const float* __restrict__ bx,
    const float* __restrict__ Ws, const float* __restrict__ bs,
    const float* __restrict__ temp, int nqx, int preBlocks)
{
    int tid = threadIdx.x;
    if ((int)blockIdx.x < preBlocks) {
        int i = blockIdx.x * 256 + tid;
        if (i < NH * 64 * 64) g_tokens[i] = 0.f;
        if (i < NH * 64) g_norm[i] = 0.f;
        if (i < nqx) {
            float4 v = reinterpret_cast<const float4*>(x)[i];
            reinterpret_cast<uint2*>(g_x_bf)[i] = make_uint2(pk(v.x, v.y), pk(v.z, v.w));
        } else if (i < nqx + WFX_QUADS) {
            int j = i - nqx;
            float4 v = reinterpret_cast<const float4*>(Wfx)[j];
            reinterpret_cast<uint2*>(g_Wfx_bf)[j] = make_uint2(pk(v.x, v.y), pk(v.z, v.w));
        }
        return;
    }

    // ---- prep1 part: Wls[hg][k] = t[h]*sum_d Ws[g][d]*Wx[h*64+d][k] ----
    __shared__ float Wss[64][64];
    __shared__ float Wxs[64][17];
    int bxid = blockIdx.x - preBlocks;     // 0..255
    int kb = bxid & 31, h = bxid >> 5;
    for (int e = tid; e < 64 * 64; e += 256) Wss[e >> 6][e & 63] = Ws[e];
    for (int e = tid; e < 64 * 16; e += 256) {
        int d = e >> 4, k = e & 15;
        Wxs[d][k] = Wx[(size_t)(h * 64 + d) * HID + kb * 16 + k];
    }
    __syncthreads();
    int g = tid >> 2, q = tid & 3;
    float t = temp[h];
#pragma unroll
    for (int kp = 0; kp < 4; kp += 2) {
        int k = q * 4 + kp;
        float s0 = 0.f, s1 = 0.f;
#pragma unroll
        for (int d = 0; d < 64; ++d) {
            float wv = Wss[g][d];
            s0 = fmaf(wv, Wxs[d][k], s0);
            s1 = fmaf(wv, Wxs[d][k + 1], s1);
        }
        g_Wls_bf[(size_t)(h * 64 + g) * 256 + kb * 8 + (k >> 1)] = pk(t * s0, t * s1);
    }
    if (kb == 0 && q == 0) {
        float s = 0.f;
#pragma unroll
        for (int d = 0; d < 64; ++d) s = fmaf(Wss[g][d], bx[h * 64 + d], s);
        g_bls[h * 64 + g] = t * (s + bs[g]);
    }
}

// ---------------------------------------------------------------------------
// bf16 mma GEMM: block 128x128, 4 warps x (64x64), K=512 (8x64),
// cp.async 2-stage, ONE barrier per chunk (issue moved after barrier),
// register-level fragment double buffering.
// mode 0: C = A@B^T + bias (fp32 out)
// mode 1: jt<4 -> temperature-softmax -> g_w_bf ; jt>=4 -> +bias -> g_fx_bf
#define SH 72
#define STAGE_B2 (128 * SH * 2)              // 18432 bytes
#define SMEM_GEMM (2 * 2 * STAGE_B2)         // 73728

__global__ __launch_bounds__(128, 2) void k_gemm(
    const uint16_t* __restrict__ A,
    const uint16_t* __restrict__ B0, const uint16_t* __restrict__ B1,
    const float* __restrict__ bias0, const float* __restrict__ bias1,
    int splitJ, int mode, float* __restrict__ Cf, int n)
{
    extern __shared__ __align__(16) unsigned char smraw[];
    uint32_t sb = smem_u32(smraw);

    int tid = threadIdx.x;
    int wid = tid >> 5, lane = tid & 31;
    int grp = lane >> 2, q = lane & 3;
    int wm = wid & 1, wn = wid >> 1;
    int l8 = lane & 7, seg = lane >> 3;

    int jt = blockIdx.x;
    int row0 = blockIdx.y * 128;
    const uint16_t* B = (jt < splitJ) ? B0 + (size_t)jt * 128 * HID
                                      : B1 + (size_t)(jt - splitJ) * 128 * HID;
    int col0 = jt * 128;

    float acc[4][8][4];
#pragma unroll
    for (int a = 0; a < 4; ++a)
#pragma unroll
        for (int b = 0; b < 8; ++b)
#pragma unroll
            for (int r = 0; r < 4; ++r) acc[a][b][r] = 0.f;

    auto issue = [&](int c, int stg) {
        int k0 = c * 64;
        uint32_t base = sb + stg * (2 * STAGE_B2);
#pragma unroll
        for (int it = 0; it < 16; ++it) {
            int slot = tid + it * 128;
            int isB = slot >> 10;
            int sl = slot & 1023;
            int r = sl >> 3, c8 = sl & 7;
            uint32_t dst = base + isB * STAGE_B2 + (uint32_t)(r * (SH * 2) + c8 * 16);
            if (!isB) {
                int gr = row0 + r;
                const uint16_t* src = A + ((gr < n) ? ((size_t)gr * HID + k0 + c8 * 8) : 0);
                cp_async16(dst, src, (gr < n) ? 16 : 0);
            } else {
                cp_async16(dst, B + (size_t)r * HID + k0 + c8 * 8, 16);
            }
        }
        cp_commit();
    };

    issue(0, 0);

    int mbase = wm * 64, nbase = wn * 64;
    uint32_t a_off0 = (uint32_t)((mbase + (seg & 1) * 8 + l8) * 144 + ((seg >> 1) * 8) * 2);
    uint32_t b_off0 = (uint32_t)((nbase + (seg >> 1) * 8 + l8) * 144 + ((seg & 1) * 8) * 2);

    uint32_t af[2][4][4], bf[2][4][4];

    auto load_frags = [&](uint32_t Abase, uint32_t Bbase, int s, int buf) {
        uint32_t ao = Abase + a_off0 + (uint32_t)(s * 32);
        uint32_t bo = Bbase + b_off0 + (uint32_t)(s * 32);
#pragma unroll
        for (int tm = 0; tm < 4; ++tm)
            ldm_x4(af[buf][tm], ao + (uint32_t)(tm * 16 * 144));
#pragma unroll
        for (int p = 0; p < 4; ++p)
            ldm_x4(bf[buf][p], bo + (uint32_t)(p * 16 * 144));
    };
    auto do_mma = [&](int buf) {
#pragma unroll
        for (int nt = 0; nt < 8; ++nt) {
            uint32_t b0 = bf[buf][nt >> 1][(nt & 1) * 2];
            uint32_t b1 = bf[buf][nt >> 1][(nt & 1) * 2 + 1];
#pragma unroll
            for (int tm = 0; tm < 4; ++tm)
                mma_bf16(acc[tm][nt], af[buf][tm][0], af[buf][tm][1],
                         af[buf][tm][2], af[buf][tm][3], b0, b1);
        }
    };

    for (int c = 0; c < 8; ++c) {
        int stg = c & 1;
        cp_wait<0>();                 // chunk c arrived (this thread's groups)
        __syncthreads();              // publish c; all warps done reading stg^1
        if (c < 7) issue(c + 1, stg ^ 1);   // WAR-safe: after barrier

        uint32_t Abase = sb + stg * (2 * STAGE_B2);
        uint32_t Bbase = Abase + STAGE_B2;

        load_frags(Abase, Bbase, 0, 0);
#pragma unroll
        for (int s = 0; s < 4; ++s) {
            int cur = s & 1;
            if (s < 3) load_frags(Abase, Bbase, s + 1, cur ^ 1);
            do_mma(cur);
        }
    }

    // ---- epilogue (registers only; no smem reads) --------------------------
    const float* bias = (jt < splitJ) ? bias0 + jt * 128 : bias1 + (jt - splitJ) * 128;

    if (mode == 0) {
#pragma unroll
        for (int tm = 0; tm < 4; ++tm) {
            int r0 = row0 + wm * 64 + tm * 16 + grp;
#pragma unroll
            for (int nt = 0; nt < 8; ++nt) {
                int cl = wn * 64 + nt * 8 + q * 2;
                float b0 = bias[cl], b1 = bias[cl + 1];
                if (r0 < n) {
                    float2 v = make_float2(acc[tm][nt][0] + b0, acc[tm][nt][1] + b1);
                    *reinterpret_cast<float2*>(&Cf[(size_t)r0 * HID + col0 + cl]) = v;
                }
                if (r0 + 8 < n) {
                    float2 v = make_float2(acc[tm][nt][2] + b0, acc[tm][nt][3] + b1);
                    *reinterpret_cast<float2*>(&Cf[(size_t)(r0 + 8) * HID + col0 + cl]) = v;
                }
            }
        }
        return;
    }

    if (jt < splitJ) {
#pragma unroll
        for (int tm = 0; tm < 4; ++tm) {
            float mx0 = -1e30f, mx1 = -1e30f;
#pragma unroll
            for (int nt = 0; nt < 8; ++nt) {
                int cl = wn * 64 + nt * 8 + q * 2;
                float b0 = bias[cl], b1 = bias[cl + 1];
                acc[tm][nt][0] += b0; acc[tm][nt][1] += b1;
                acc[tm][nt][2] += b0; acc[tm][nt][3] += b1;
                mx0 = fmaxf(mx0, fmaxf(acc[tm][nt][0], acc[tm][nt][1]));
                mx1 = fmaxf(mx1, fmaxf(acc[tm][nt][2], acc[tm][nt][3]));
            }
            mx0 = fmaxf(mx0, __shfl_xor_sync(0xffffffffu, mx0, 1));
            mx0 = fmaxf(mx0, __shfl_xor_sync(0xffffffffu, mx0, 2));
            mx1 = fmaxf(mx1, __shfl_xor_sync(0xffffffffu, mx1, 1));
            mx1 = fmaxf(mx1, __shfl_xor_sync(0xffffffffu, mx1, 2));
            float s0 = 0.f, s1 = 0.f;
#pragma unroll
            for (int nt = 0; nt < 8; ++nt) {
                acc[tm][nt][0] = __expf(acc[tm][nt][0] - mx0);
                acc[tm][nt][1] = __expf(acc[tm][nt][1] - mx0);
                acc[tm][nt][2] = __expf(acc[tm][nt][2] - mx1);
                acc[tm][nt][3] = __expf(acc[tm][nt][3] - mx1);
                s0 += acc[tm][nt][0] + acc[tm][nt][1];
                s1 += acc[tm][nt][2] + acc[tm][nt][3];
            }
            s0 += __shfl_xor_sync(0xffffffffu, s0, 1);
            s0 += __shfl_xor_sync(0xffffffffu, s0, 2);
            s1 += __shfl_xor_sync(0xffffffffu, s1, 1);
            s1 += __shfl_xor_sync(0xffffffffu, s1, 2);
            float i0 = 1.f / s0, i1 = 1.f / s1;
            int r0 = row0 + wm * 64 + tm * 16 + grp;
#pragma unroll
            for (int nt = 0; nt < 8; ++nt) {
                int w32 = (col0 + wn * 64 + nt * 8 + q * 2) >> 1;
                if (r0 < n)
                    g_w_bf[(size_t)r0 * 256 + w32] =
                        pk(acc[tm][nt][0] * i0, acc[tm][nt][1] * i0);
                if (r0 + 8 < n)
                    g_w_bf[(size_t)(r0 + 8) * 256 + w32] =
                        pk(acc[tm][nt][2] * i1, acc[tm][nt][3] * i1);
            }
        }
    } else {
#pragma unroll
        for (int tm = 0; tm < 4; ++tm) {
            int r0 = row0 + wm * 64 + tm * 16 + grp;
#pragma unroll
            for (int nt = 0; nt < 8; ++nt) {
                int cl = wn * 64 + nt * 8 + q * 2;
                float b0 = bias[cl], b1 = bias[cl + 1];
                int f32i = ((jt - splitJ) * 128 + cl) >> 1;
                if (r0 < n)
                    g_fx_bf[(size_t)r0 * 256 + f32i] =
                        pk(acc[tm][nt][0] + b0, acc[tm][nt][1] + b1);
                if (r0 + 8 < n)
                    g_fx_bf[(size_t)(r0 + 8) * 256 + f32i] =
                        pk(acc[tm][nt][2] + b0, acc[tm][nt][3] + b1);
            }
        }
    }
}

// ---------------------------------------------------------------------------
// pooling via bf16 mma split-K, grid (144, NH), 128 threads.
// Same single-barrier-per-chunk transform.
#define PSH 72
#define PSTAGE (64 * PSH * 2)
#define PBLK 144

__global__ __launch_bounds__(128) void k_pool(int n) {
    __shared__ __align__(16) unsigned char psm[2 * 2 * PSTAGE];
    uint32_t sb = smem_u32(psm);
    uint32_t* smw = reinterpret_cast<uint32_t*>(psm);

    int h = blockIdx.y;
    int cta = blockIdx.x;
    int tid = threadIdx.x;
    int wid = tid >> 5, lane = tid & 31;
    int grp = lane >> 2, q = lane & 3;

    int per = (((n + PBLK - 1) / PBLK) + 63) & ~63;
    int nstart = cta * per;
    int nend = min(nstart + per, n);

    for (int i = tid; i < 2 * 64 * 4; i += 128) {
        int stg = i >> 8, rw = (i >> 2) & 63, pw = i & 3;
        uint32_t* fxs = smw + (stg * 2 * PSTAGE + PSTAGE) / 4;
        fxs[rw * 36 + 32 + pw] = (pw == 0) ? 0x00003F80u : 0u;
    }
    __syncthreads();   // pad columns visible before first mma

    float acc[9][4];
#pragma unroll
    for (int a = 0; a < 9; ++a)
#pragma unroll
        for (int r = 0; r < 4; ++r) acc[a][r] = 0.f;

    int nchunks = (nend > nstart) ? ((nend - nstart + 63) >> 6) : 0;

    auto issue = [&](int c, int stg) {
        int n0 = nstart + c * 64;
        uint32_t base = sb + stg * (2 * PSTAGE);
#pragma unroll
        for (int it = 0; it < 8; ++it) {
            int slot = tid + it * 128;
            int isF = slot >> 9;
            int sl = slot & 511;
            int r = sl >> 3, c8 = sl & 7;
            uint32_t dst = base + isF * PSTAGE + (uint32_t)(r * (PSH * 2) + c8 * 16);
            int gr = n0 + r;
            const uint32_t* src = (isF ? g_fx_bf : g_w_bf) +
                                  ((gr < nend) ? ((size_t)gr * 256 + h * 32 + c8 * 4) : 0);
            cp_async16(dst, src, (gr < nend) ? 16 : 0);
        }
        cp_commit();
    };

    if (nchunks > 0) issue(0, 0);

    for (int c = 0; c < nchunks; ++c) {
        int stg = c & 1;
        cp_wait<0>();
        __syncthreads();
        if (c + 1 < nchunks) issue(c + 1, stg ^ 1);

        uint32_t wbase = sb + stg * (2 * PSTAGE);
        uint32_t fbase = wbase + PSTAGE;
        int g0 = wid * 16;

#pragma unroll
        for (int s = 0; s < 4; ++s) {
            int k0 = s * 16;
            int kk = k0 + (lane & 7) + ((lane >> 4) << 3);
            int gg = g0 + (((lane >> 3) & 1) << 3);
            uint32_t af2[4];
            ldm_x4t(af2, wbase + (uint32_t)(kk * (PSH * 2) + gg * 2));
#pragma unroll
            for (int nt = 0; nt < 9; ++nt) {
                int kb = k0 + (lane & 15);
                uint32_t b0, b1;
                ldm_x2t(b0, b1, fbase + (uint32_t)(kb * (PSH * 2) + nt * 16));
                mma_bf16(acc[nt], af2[0], af2[1], af2[2], af2[3], b0, b1);
            }
        }
    }

    int g = wid * 16 + grp;
#pragma unroll
    for (int nt = 0; nt < 9; ++nt) {
        int d = nt * 8 + q * 2;
        if (nt < 8) {
            atomicAdd(&g_tokens[h * 4096 + g * 64 + d], acc[nt][0]);
            atomicAdd(&g_tokens[h * 4096 + g * 64 + d + 1], acc[nt][1]);
            atomicAdd(&g_tokens[h * 4096 + (g + 8) * 64 + d], acc[nt][2]);
            atomicAdd(&g_tokens[h * 4096 + (g + 8) * 64 + d + 1], acc[nt][3]);
        } else if (q == 0) {
            atomicAdd(&g_norm[h * 64 + g], acc[nt][0]);
            atomicAdd(&g_norm[h * 64 + g + 8], acc[nt][2]);
        }
    }
}

// ---------------------------------------------------------------------------
// slice attention per head; writes out_tok to g_ot.
__global__ __launch_bounds__(256) void k_attn(
    const float* __restrict__ Wq, const float* __restrict__ Wk,
    const float* __restrict__ Wv, const float* __restrict__ Wo)
{
    __shared__ float tok[64][65];
    __shared__ float qs[64][65];
    __shared__ float ks[64][65];
    __shared__ float vs[64][65];
    __shared__ float ss[64][65];

    int h = blockIdx.x;
    int tid = threadIdx.x;
    int g = tid >> 2, q = tid & 3;

    for (int e = tid; e < 64 * 64; e += 256) {
        int gg = e >> 6, d = e & 63;
        tok[gg][d] = g_tokens[h * 4096 + e] * (1.f / (g_norm[h * 64 + gg] + EPS));
    }
    __syncthreads();

#pragma unroll
    for (int oi = 0; oi < 16; ++oi) {
        int o = q * 16 + oi;
        float sq = 0.f, sk = 0.f, sv = 0.f;
#pragma unroll
        for (int d = 0; d < 64; ++d) {
            float tv = tok[g][d];
            sq = fmaf(tv, Wq[o * 64 + d], sq);
            sk = fmaf(tv, Wk[o * 64 + d], sk);
            sv = fmaf(tv, Wv[o * 64 + d], sv);
        }
        qs[g][o] = sq; ks[g][o] = sk; vs[g][o] = sv;
    }
    __syncthreads();

    float sj[16];
    float mx = -1e30f;
#pragma unroll
    for (int ji = 0; ji < 16; ++ji) {
        int j = q * 16 + ji;
        float t = 0.f;
#pragma unroll
        for (int o = 0; o < 64; ++o) t = fmaf(qs[g][o], ks[j][o], t);
        t *= 0.125f;
        sj[ji] = t;
        mx = fmaxf(mx, t);
    }
    mx = fmaxf(mx, __shfl_xor_sync(0xffffffffu, mx, 1));
    mx = fmaxf(mx, __shfl_xor_sync(0xffffffffu, mx, 2));
    float sum = 0.f;
#pragma unroll
    for (int ji = 0; ji < 16; ++ji) { sj[ji] = __expf(sj[ji] - mx); sum += sj[ji]; }
    sum += __shfl_xor_sync(0xffffffffu, sum, 1);
    sum += __shfl_xor_sync(0xffffffffu, sum, 2);
    float inv = 1.f / sum;
#pragma unroll
    for (int ji = 0; ji < 16; ++ji) ss[g][q * 16 + ji] = sj[ji];
    __syncthreads();

#pragma unroll
    for (int di = 0; di < 16; ++di) {
        int d = q * 16 + di;
        float t = 0.f;
#pragma unroll
        for (int j = 0; j < 64; ++j) t = fmaf(ss[g][j], vs[j][d], t);
        tok[g][d] = t * inv;
    }
    __syncthreads();

#pragma unroll
    for (int oi = 0; oi < 16; ++oi) {
        int o = q * 16 + oi;
        float t = 0.f;
#pragma unroll
        for (int d = 0; d < 64; ++d) t = fmaf(tok[g][d], Wo[o * 64 + d], t);
        g_ot[h * 4096 + g * 64 + o] = t;
    }
}

// ---------------------------------------------------------------------------
// prep2 (parallel): P[o][hg] = sum_d Wout[o][h*64+d] * ot[h][g][d] -> bf16
__global__ __launch_bounds__(256) void k_prep2(const float* __restrict__ Wout) {
    __shared__ float ots[64][65];
    int h = blockIdx.x, ob = blockIdx.y;
    int tid = threadIdx.x;
    for (int e = tid; e < 64 * 64; e += 256)
        ots[e >> 6][e & 63] = g_ot[h * 4096 + e];
    __syncthreads();
    int o = ob * 64 + (tid >> 2), q = tid & 3;
    float wr[64];
#pragma unroll
    for (int d = 0; d < 64; ++d) wr[d] = Wout[(size_t)o * HID + h * 64 + d];
#pragma unroll
    for (int gg = q * 16; gg < q * 16 + 16; gg += 2) {
        float s0 = 0.f, s1 = 0.f;
#pragma unroll
        for (int d = 0; d < 64; ++d) {
            s0 = fmaf(wr[d], ots[gg][d], s0);
            s1 = fmaf(wr[d], ots[gg + 1][d], s1);
        }
        g_P_bf[(size_t)o * 256 + h * 32 + (gg >> 1)] = pk(s0, s1);
    }
}

// ---------------------------------------------------------------------------
extern "C" void kernel_launch(void* const* d_in, const int* in_sizes, int n_in,
                              void* d_out, int out_size) {
    const float* x    = (const float*)d_in[0];
    const float* Wx   = (const float*)d_in[1];
    const float* bx   = (const float*)d_in[2];
    const float* Wfx  = (const float*)d_in[3];
    const float* bfx  = (const float*)d_in[4];
    const float* Ws   = (const float*)d_in[5];
    const float* bs   = (const float*)d_in[6];
    const float* temp = (const float*)d_in[7];
    const float* Wq   = (const float*)d_in[8];
    const float* Wk   = (const float*)d_in[9];
    const float* Wv   = (const float*)d_in[10];
    const float* Wo   = (const float*)d_in[11];
    const float* Wout = (const float*)d_in[12];
    const float* bout = (const float*)d_in[13];
    float* out = (float*)d_out;

    int n = in_sizes[0] / HID;
    int mtiles = (n + 127) / 128;

    uint32_t *wfxbf, *wlsbf, *wbf, *pbf, *xbf;
    float *bls;
    cudaGetSymbolAddress((void**)&wfxbf, g_Wfx_bf);
    cudaGetSymbolAddress((void**)&wlsbf, g_Wls_bf);
    cudaGetSymbolAddress((void**)&wbf, g_w_bf);
    cudaGetSymbolAddress((void**)&pbf, g_P_bf);
    cudaGetSymbolAddress((void**)&bls, g_bls);
    cudaGetSymbolAddress((void**)&xbf, g_x_bf);

    cudaFuncSetAttribute(k_gemm, cudaFuncAttributeMaxDynamicSharedMemorySize, SMEM_GEMM);

    int nqx = n * 128;   // float4 quads in x
    int preBlocks = (nqx + WFX_QUADS + 255) / 256;
    k_pre<<<preBlocks + 256, 256>>>(x, Wfx, Wx, bx, Ws, bs, temp, nqx, preBlocks);

    // GEMM1 (mode 1)
    dim3 gg1(8, mtiles);
    k_gemm<<<gg1, 128, SMEM_GEMM>>>(
        (const uint16_t*)xbf, (const uint16_t*)wlsbf, (const uint16_t*)wfxbf,
        bls, bfx, 4, 1, nullptr, n);

    dim3 gpool(PBLK, NH);
    k_pool<<<gpool, 128>>>(n);

    k_attn<<<NH, 256>>>(Wq, Wk, Wv, Wo);

    dim3 gp2(NH, 8);
    k_prep2<<<gp2, 256>>>(Wout);

    // GEMM2 (mode 0)
    dim3 gg2(4, mtiles);
    k_gemm<<<gg2, 128, SMEM_GEMM>>>(
        (const uint16_t*)wbf, (const uint16_t*)pbf, (const uint16_t*)pbf,
        bout, bout, 4, 0, out, n);
}

// round 17
// speedup vs baseline: 1.1533x; 1.1533x over previous
#include <cuda_runtime.h>
#include <cstdint>
#include <math.h>

#define HID 512
#define NH 8
#define MAXN 100000
#define EPS 1e-5f

// ---------------- scratch (device globals) ---------------------------------
__device__ uint32_t g_x_bf[(size_t)MAXN * 256];    // x bf16 [n][512]
__device__ uint32_t g_fx_bf[(size_t)MAXN * 256];   // fx bf16 [n][512]
__device__ uint32_t g_w_bf[(size_t)MAXN * 256];    // softmax w bf16 [n][512]
__device__ uint32_t g_Wls_bf[512 * 256];           // folded logits W bf16 [hg][512]
__device__ uint32_t g_Wfx_bf[512 * 256];           // Wfx bf16
__device__ uint32_t g_P_bf[512 * 256];             // folded unpool+outproj bf16 [o][hg]
__device__ float g_bls[512];
__device__ float g_tokens[NH * 64 * 64];
__device__ float g_norm[NH * 64];
__device__ float g_ot[NH * 64 * 64];               // out_tok (attn output)

// ---------------- helpers ---------------------------------------------------
__device__ __forceinline__ uint32_t smem_u32(const void* p) {
    uint32_t a;
    asm("{ .reg .u64 t; cvta.to.shared.u64 t, %1; cvt.u32.u64 %0, t; }" : "=r"(a) : "l"(p));
    return a;
}
__device__ __forceinline__ uint32_t pk(float lo, float hi) {
    uint32_t r;
    asm("cvt.rn.bf16x2.f32 %0, %1, %2;" : "=r"(r) : "f"(hi), "f"(lo));
    return r;
}
__device__ __forceinline__ void cp_async16(uint32_t dst, const void* src, int sz) {
    asm volatile("cp.async.ca.shared.global [%0], [%1], 16, %2;"
                 :: "r"(dst), "l"(src), "r"(sz));
}
__device__ __forceinline__ void cp_commit() {
    asm volatile("cp.async.commit_group;" ::: "memory");
}
template <int N>
__device__ __forceinline__ void cp_wait() {
    asm volatile("cp.async.wait_group %0;" :: "n"(N) : "memory");
}
__device__ __forceinline__ void mma_bf16(float* c, uint32_t a0, uint32_t a1,
                                         uint32_t a2, uint32_t a3,
                                         uint32_t b0, uint32_t b1) {
    asm volatile(
        "mma.sync.aligned.m16n8k16.row.col.f32.bf16.bf16.f32 "
        "{%0,%1,%2,%3}, {%4,%5,%6,%7}, {%8,%9}, {%0,%1,%2,%3};"
        : "+f"(c[0]), "+f"(c[1]), "+f"(c[2]), "+f"(c[3])
        : "r"(a0), "r"(a1), "r"(a2), "r"(a3), "r"(b0), "r"(b1));
}
__device__ __forceinline__ void ldm_x4(uint32_t* r, uint32_t addr) {
    asm volatile("ldmatrix.sync.aligned.m8n8.x4.shared.b16 {%0,%1,%2,%3}, [%4];"
                 : "=r"(r[0]), "=r"(r[1]), "=r"(r[2]), "=r"(r[3]) : "r"(addr));
}
__device__ __forceinline__ void ldm_x4t(uint32_t* r, uint32_t addr) {
    asm volatile("ldmatrix.sync.aligned.m8n8.x4.trans.shared.b16 {%0,%1,%2,%3}, [%4];"
                 : "=r"(r[0]), "=r"(r[1]), "=r"(r[2]), "=r"(r[3]) : "r"(addr));
}
__device__ __forceinline__ void ldm_x2t(uint32_t& r0, uint32_t& r1, uint32_t addr) {
    asm volatile("ldmatrix.sync.aligned.m8n8.x2.trans.shared.b16 {%0,%1}, [%2];"
                 : "=r"(r0), "=r"(r1) : "r"(addr));
}

// ---------------------------------------------------------------------------
// k_pre: zero token/norm accumulators; x fp32->bf16 (vectorized); Wfx -> bf16.
#define WFX_QUADS 65536

__global__ void k_pre(const float* __restrict__ x, const float* __restrict__ Wfx,
                      int nqx) {
    int i = blockIdx.x * blockDim.x + threadIdx.x;
    if (i < NH * 64 * 64) g_tokens[i] = 0.f;
    if (i < NH * 64) g_norm[i] = 0.f;
    if (i < nqx) {
        float4 v = reinterpret_cast<const float4*>(x)[i];
        reinterpret_cast<uint2*>(g_x_bf)[i] = make_uint2(pk(v.x, v.y), pk(v.z, v.w));
    } else if (i < nqx + WFX_QUADS) {
        int j = i - nqx;
        float4 v = reinterpret_cast<const float4*>(Wfx)[j];
        reinterpret_cast<uint2*>(g_Wfx_bf)[j] = make_uint2(pk(v.x, v.y), pk(v.z, v.w));
    }
}

// ---------------------------------------------------------------------------
// prep1: Wls[hg][k] = t[h]*sum_d Ws[g][d]*Wx[h*64+d][k]  (bf16), grid (32, NH)
__global__ __launch_bounds__(256) void k_prep1(
    const float* __restrict__ Wx, const float* __restrict__ bx,
    const float* __restrict__ Ws, const float* __restrict__ bs,
    const float* __restrict__ temp)
{
    __shared__ float Wss[64][64];
    __shared__ float Wxs[64][17];
    int kb = blockIdx.x, h = blockIdx.y;
    int tid = threadIdx.x;
    for (int e = tid; e < 64 * 64; e += 256) Wss[e >> 6][e & 63] = Ws[e];
    for (int e = tid; e < 64 * 16; e += 256) {
        int d = e >> 4, k = e & 15;
        Wxs[d][k] = Wx[(size_t)(h * 64 + d) * HID + kb * 16 + k];
    }
    __syncthreads();
    int g = tid >> 2, q = tid & 3;
    float t = temp[h];
#pragma unroll
    for (int kp = 0; kp < 4; kp += 2) {
        int k = q * 4 + kp;
        float s0 = 0.f, s1 = 0.f;
#pragma unroll
        for (int d = 0; d < 64; ++d) {
            float wv = Wss[g][d];
            s0 = fmaf(wv, Wxs[d][k], s0);
            s1 = fmaf(wv, Wxs[d][k + 1], s1);
        }
        g_Wls_bf[(size_t)(h * 64 + g) * 256 + kb * 8 + (k >> 1)] = pk(t * s0, t * s1);
    }
    if (kb == 0 && q == 0) {
        float s = 0.f;
#pragma unroll
        for (int d = 0; d < 64; ++d) s = fmaf(Wss[g][d], bx[h * 64 + d], s);
        g_bls[h * 64 + g] = t * (s + bs[g]);
    }
}

// ---------------------------------------------------------------------------
// bf16 mma GEMM (r15-proven loop): block 128x128, 4 warps x (64x64), K=512,
// cp.async 2-stage + register fragment double buffering.
#define SH 72
#define STAGE_B2 (128 * SH * 2)              // 18432 bytes
#define SMEM_GEMM (2 * 2 * STAGE_B2)         // 73728

__global__ __launch_bounds__(128, 2) void k_gemm(
    const uint16_t* __restrict__ A,
    const uint16_t* __restrict__ B0, const uint16_t* __restrict__ B1,
    const float* __restrict__ bias0, const float* __restrict__ bias1,
    int splitJ, int mode, float* __restrict__ Cf, int n)
{
    extern __shared__ __align__(16) unsigned char smraw[];
    uint32_t sb = smem_u32(smraw);

    int tid = threadIdx.x;
    int wid = tid >> 5, lane = tid & 31;
    int grp = lane >> 2, q = lane & 3;
    int wm = wid & 1, wn = wid >> 1;
    int l8 = lane & 7, seg = lane >> 3;

    int jt = blockIdx.x;
    int row0 = blockIdx.y * 128;
    const uint16_t* B = (jt < splitJ) ? B0 + (size_t)jt * 128 * HID
                                      : B1 + (size_t)(jt - splitJ) * 128 * HID;
    int col0 = jt * 128;

    float acc[4][8][4];
#pragma unroll
    for (int a = 0; a < 4; ++a)
#pragma unroll
        for (int b = 0; b < 8; ++b)
#pragma unroll
            for (int r = 0; r < 4; ++r) acc[a][b][r] = 0.f;

    auto issue = [&](int c, int stg) {
        int k0 = c * 64;
        uint32_t base = sb + stg * (2 * STAGE_B2);
#pragma unroll
        for (int it = 0; it < 16; ++it) {
            int slot = tid + it * 128;
            int isB = slot >> 10;
            int sl = slot & 1023;
            int r = sl >> 3, c8 = sl & 7;
            uint32_t dst = base + isB * STAGE_B2 + (uint32_t)(r * (SH * 2) + c8 * 16);
            if (!isB) {
                int gr = row0 + r;
                const uint16_t* src = A + ((gr < n) ? ((size_t)gr * HID + k0 + c8 * 8) : 0);
                cp_async16(dst, src, (gr < n) ? 16 : 0);
            } else {
                cp_async16(dst, B + (size_t)r * HID + k0 + c8 * 8, 16);
            }
        }
        cp_commit();
    };

    issue(0, 0);

    int mbase = wm * 64, nbase = wn * 64;
    uint32_t a_off0 = (uint32_t)((mbase + (seg & 1) * 8 + l8) * 144 + ((seg >> 1) * 8) * 2);
    uint32_t b_off0 = (uint32_t)((nbase + (seg >> 1) * 8 + l8) * 144 + ((seg & 1) * 8) * 2);

    uint32_t af[2][4][4], bf[2][4][4];

    auto load_frags = [&](uint32_t Abase, uint32_t Bbase, int s, int buf) {
        uint32_t ao = Abase + a_off0 + (uint32_t)(s * 32);
        uint32_t bo = Bbase + b_off0 + (uint32_t)(s * 32);
#pragma unroll
        for (int tm = 0; tm < 4; ++tm)
            ldm_x4(af[buf][tm], ao + (uint32_t)(tm * 16 * 144));
#pragma unroll
        for (int p = 0; p < 4; ++p)
            ldm_x4(bf[buf][p], bo + (uint32_t)(p * 16 * 144));
    };
    auto do_mma = [&](int buf) {
#pragma unroll
        for (int nt = 0; nt < 8; ++nt) {
            uint32_t b0 = bf[buf][nt >> 1][(nt & 1) * 2];
            uint32_t b1 = bf[buf][nt >> 1][(nt & 1) * 2 + 1];
#pragma unroll
            for (int tm = 0; tm < 4; ++tm)
                mma_bf16(acc[tm][nt], af[buf][tm][0], af[buf][tm][1],
                         af[buf][tm][2], af[buf][tm][3], b0, b1);
        }
    };

    for (int c = 0; c < 8; ++c) {
        int stg = c & 1;
        if (c < 7) { issue(c + 1, stg ^ 1); cp_wait<1>(); }
        else       { cp_wait<0>(); }
        __syncthreads();

        uint32_t Abase = sb + stg * (2 * STAGE_B2);
        uint32_t Bbase = Abase + STAGE_B2;

        load_frags(Abase, Bbase, 0, 0);
#pragma unroll
        for (int s = 0; s < 4; ++s) {
            int cur = s & 1;
            if (s < 3) load_frags(Abase, Bbase, s + 1, cur ^ 1);
            do_mma(cur);
        }
        __syncthreads();
    }

    // ---- epilogue ----------------------------------------------------------
    const float* bias = (jt < splitJ) ? bias0 + jt * 128 : bias1 + (jt - splitJ) * 128;

    if (mode == 0) {
#pragma unroll
        for (int tm = 0; tm < 4; ++tm) {
            int r0 = row0 + wm * 64 + tm * 16 + grp;
#pragma unroll
            for (int nt = 0; nt < 8; ++nt) {
                int cl = wn * 64 + nt * 8 + q * 2;
                float b0 = bias[cl], b1 = bias[cl + 1];
                if (r0 < n) {
                    float2 v = make_float2(acc[tm][nt][0] + b0, acc[tm][nt][1] + b1);
                    *reinterpret_cast<float2*>(&Cf[(size_t)r0 * HID + col0 + cl]) = v;
                }
                if (r0 + 8 < n) {
                    float2 v = make_float2(acc[tm][nt][2] + b0, acc[tm][nt][3] + b1);
                    *reinterpret_cast<float2*>(&Cf[(size_t)(r0 + 8) * HID + col0 + cl]) = v;
                }
            }
        }
        return;
    }

    if (jt < splitJ) {
#pragma unroll
        for (int tm = 0; tm < 4; ++tm) {
            float mx0 = -1e30f, mx1 = -1e30f;
#pragma unroll
            for (int nt = 0; nt < 8; ++nt) {
                int cl = wn * 64 + nt * 8 + q * 2;
                float b0 = bias[cl], b1 = bias[cl + 1];
                acc[tm][nt][0] += b0; acc[tm][nt][1] += b1;
                acc[tm][nt][2] += b0; acc[tm][nt][3] += b1;
                mx0 = fmaxf(mx0, fmaxf(acc[tm][nt][0], acc[tm][nt][1]));
                mx1 = fmaxf(mx1, fmaxf(acc[tm][nt][2], acc[tm][nt][3]));
            }
            mx0 = fmaxf(mx0, __shfl_xor_sync(0xffffffffu, mx0, 1));
            mx0 = fmaxf(mx0, __shfl_xor_sync(0xffffffffu, mx0, 2));
            mx1 = fmaxf(mx1, __shfl_xor_sync(0xffffffffu, mx1, 1));
            mx1 = fmaxf(mx1, __shfl_xor_sync(0xffffffffu, mx1, 2));
            float s0 = 0.f, s1 = 0.f;
#pragma unroll
            for (int nt = 0; nt < 8; ++nt) {
                acc[tm][nt][0] = __expf(acc[tm][nt][0] - mx0);
                acc[tm][nt][1] = __expf(acc[tm][nt][1] - mx0);
                acc[tm][nt][2] = __expf(acc[tm][nt][2] - mx1);
                acc[tm][nt][3] = __expf(acc[tm][nt][3] - mx1);
                s0 += acc[tm][nt][0] + acc[tm][nt][1];
                s1 += acc[tm][nt][2] + acc[tm][nt][3];
            }
            s0 += __shfl_xor_sync(0xffffffffu, s0, 1);
            s0 += __shfl_xor_sync(0xffffffffu, s0, 2);
            s1 += __shfl_xor_sync(0xffffffffu, s1, 1);
            s1 += __shfl_xor_sync(0xffffffffu, s1, 2);
            float i0 = 1.f / s0, i1 = 1.f / s1;
            int r0 = row0 + wm * 64 + tm * 16 + grp;
#pragma unroll
            for (int nt = 0; nt < 8; ++nt) {
                int w32 = (col0 + wn * 64 + nt * 8 + q * 2) >> 1;
                if (r0 < n)
                    g_w_bf[(size_t)r0 * 256 + w32] =
                        pk(acc[tm][nt][0] * i0, acc[tm][nt][1] * i0);
                if (r0 + 8 < n)
                    g_w_bf[(size_t)(r0 + 8) * 256 + w32] =
                        pk(acc[tm][nt][2] * i1, acc[tm][nt][3] * i1);
            }
        }
    } else {
#pragma unroll
        for (int tm = 0; tm < 4; ++tm) {
            int r0 = row0 + wm * 64 + tm * 16 + grp;
#pragma unroll
            for (int nt = 0; nt < 8; ++nt) {
                int cl = wn * 64 + nt * 8 + q * 2;
                float b0 = bias[cl], b1 = bias[cl + 1];
                int f32i = ((jt - splitJ) * 128 + cl) >> 1;
                if (r0 < n)
                    g_fx_bf[(size_t)r0 * 256 + f32i] =
                        pk(acc[tm][nt][0] + b0, acc[tm][nt][1] + b1);
                if (r0 + 8 < n)
                    g_fx_bf[(size_t)(r0 + 8) * 256 + f32i] =
                        pk(acc[tm][nt][2] + b0, acc[tm][nt][3] + b1);
            }
        }
    }
}

// ---------------------------------------------------------------------------
// pooling via bf16 mma split-K, grid (144, NH), 128 threads. (r15-proven)
#define PSH 72
#define PSTAGE (64 * PSH * 2)
#define PBLK 144

__global__ __launch_bounds__(128) void k_pool(int n) {
    __shared__ __align__(16) unsigned char psm[2 * 2 * PSTAGE];
    uint32_t sb = smem_u32(psm);
    uint32_t* smw = reinterpret_cast<uint32_t*>(psm);

    int h = blockIdx.y;
    int cta = blockIdx.x;
    int tid = threadIdx.x;
    int wid = tid >> 5, lane = tid & 31;
    int grp = lane >> 2, q = lane & 3;

    int per = (((n + PBLK - 1) / PBLK) + 63) & ~63;
    int nstart = cta * per;
    int nend = min(nstart + per, n);

    for (int i = tid; i < 2 * 64 * 4; i += 128) {
        int stg = i >> 8, rw = (i >> 2) & 63, pw = i & 3;
        uint32_t* fxs = smw + (stg * 2 * PSTAGE + PSTAGE) / 4;
        fxs[rw * 36 + 32 + pw] = (pw == 0) ? 0x00003F80u : 0u;
    }

    float acc[9][4];
#pragma unroll
    for (int a = 0; a < 9; ++a)
#pragma unroll
        for (int r = 0; r < 4; ++r) acc[a][r] = 0.f;

    int nchunks = (nend > nstart) ? ((nend - nstart + 63) >> 6) : 0;

    auto issue = [&](int c, int stg) {
        int n0 = nstart + c * 64;
        uint32_t base = sb + stg * (2 * PSTAGE);
#pragma unroll
        for (int it = 0; it < 8; ++it) {
            int slot = tid + it * 128;
            int isF = slot >> 9;
            int sl = slot & 511;
            int r = sl >> 3, c8 = sl & 7;
            uint32_t dst = base + isF * PSTAGE + (uint32_t)(r * (PSH * 2) + c8 * 16);
            int gr = n0 + r;
            const uint32_t* src = (isF ? g_fx_bf : g_w_bf) +
                                  ((gr < nend) ? ((size_t)gr * 256 + h * 32 + c8 * 4) : 0);
            cp_async16(dst, src, (gr < nend) ? 16 : 0);
        }
        cp_commit();
    };

    if (nchunks > 0) issue(0, 0);

    for (int c = 0; c < nchunks; ++c) {
        int stg = c & 1;
        if (c + 1 < nchunks) { issue(c + 1, stg ^ 1); cp_wait<1>(); }
        else                 { cp_wait<0>(); }
        __syncthreads();

        uint32_t wbase = sb + stg * (2 * PSTAGE);
        uint32_t fbase = wbase + PSTAGE;
        int g0 = wid * 16;

#pragma unroll
        for (int s = 0; s < 4; ++s) {
            int k0 = s * 16;
            int kk = k0 + (lane & 7) + ((lane >> 4) << 3);
            int gg = g0 + (((lane >> 3) & 1) << 3);
            uint32_t af2[4];
            ldm_x4t(af2, wbase + (uint32_t)(kk * (PSH * 2) + gg * 2));
#pragma unroll
            for (int nt = 0; nt < 9; ++nt) {
                int kb = k0 + (lane & 15);
                uint32_t b0, b1;
                ldm_x2t(b0, b1, fbase + (uint32_t)(kb * (PSH * 2) + nt * 16));
                mma_bf16(acc[nt], af2[0], af2[1], af2[2], af2[3], b0, b1);
            }
        }
        __syncthreads();
    }

    int g = wid * 16 + grp;
#pragma unroll
    for (int nt = 0; nt < 9; ++nt) {
        int d = nt * 8 + q * 2;
        if (nt < 8) {
            atomicAdd(&g_tokens[h * 4096 + g * 64 + d], acc[nt][0]);
            atomicAdd(&g_tokens[h * 4096 + g * 64 + d + 1], acc[nt][1]);
            atomicAdd(&g_tokens[h * 4096 + (g + 8) * 64 + d], acc[nt][2]);
            atomicAdd(&g_tokens[h * 4096 + (g + 8) * 64 + d + 1], acc[nt][3]);
        } else if (q == 0) {
            atomicAdd(&g_norm[h * 64 + g], acc[nt][0]);
            atomicAdd(&g_norm[h * 64 + g + 8], acc[nt][2]);
        }
    }
}

// ---------------------------------------------------------------------------
// slice attention per head, ALL weights staged in dynamic smem (stride 65).
// smem: tok,qs,ks,vs,ss (64x65 each) + Wq,Wk,Wv,Wo (64x65 each) = 149.8 KB
#define ATTN_SMEM (9 * 64 * 65 * 4)

__global__ __launch_bounds__(256) void k_attn(
    const float* __restrict__ Wq, const float* __restrict__ Wk,
    const float* __restrict__ Wv, const float* __restrict__ Wo)
{
    extern __shared__ float asm_[];
    float (*tok)[65] = reinterpret_cast<float(*)[65]>(asm_);
    float (*qs)[65]  = reinterpret_cast<float(*)[65]>(asm_ + 1 * 4160);
    float (*ks)[65]  = reinterpret_cast<float(*)[65]>(asm_ + 2 * 4160);
    float (*vs)[65]  = reinterpret_cast<float(*)[65]>(asm_ + 3 * 4160);
    float (*ss)[65]  = reinterpret_cast<float(*)[65]>(asm_ + 4 * 4160);
    float (*Wqs)[65] = reinterpret_cast<float(*)[65]>(asm_ + 5 * 4160);
    float (*Wks)[65] = reinterpret_cast<float(*)[65]>(asm_ + 6 * 4160);
    float (*Wvs)[65] = reinterpret_cast<float(*)[65]>(asm_ + 7 * 4160);
    float (*Wos)[65] = reinterpret_cast<float(*)[65]>(asm_ + 8 * 4160);

    int h = blockIdx.x;
    int tid = threadIdx.x;
    int g = tid >> 2, q = tid & 3;

    for (int e = tid; e < 64 * 64; e += 256) {
        int r = e >> 6, d = e & 63;
        Wqs[r][d] = Wq[e];
        Wks[r][d] = Wk[e];
        Wvs[r][d] = Wv[e];
        Wos[r][d] = Wo[e];
        tok[r][d] = g_tokens[h * 4096 + e] * (1.f / (g_norm[h * 64 + r] + EPS));
    }
    __syncthreads();

#pragma unroll
    for (int oi = 0; oi < 16; ++oi) {
        int o = q * 16 + oi;
        float sq = 0.f, sk = 0.f, sv = 0.f;
#pragma unroll
        for (int d = 0; d < 64; ++d) {
            float tv = tok[g][d];
            sq = fmaf(tv, Wqs[o][d], sq);
            sk = fmaf(tv, Wks[o][d], sk);
            sv = fmaf(tv, Wvs[o][d], sv);
        }
        qs[g][o] = sq; ks[g][o] = sk; vs[g][o] = sv;
    }
    __syncthreads();

    float sj[16];
    float mx = -1e30f;
#pragma unroll
    for (int ji = 0; ji < 16; ++ji) {
        int j = q * 16 + ji;
        float t = 0.f;
#pragma unroll
        for (int o = 0; o < 64; ++o) t = fmaf(qs[g][o], ks[j][o], t);
        t *= 0.125f;
        sj[ji] = t;
        mx = fmaxf(mx, t);
    }
    mx = fmaxf(mx, __shfl_xor_sync(0xffffffffu, mx, 1));
    mx = fmaxf(mx, __shfl_xor_sync(0xffffffffu, mx, 2));
    float sum = 0.f;
#pragma unroll
    for (int ji = 0; ji < 16; ++ji) { sj[ji] = __expf(sj[ji] - mx); sum += sj[ji]; }
    sum += __shfl_xor_sync(0xffffffffu, sum, 1);
    sum += __shfl_xor_sync(0xffffffffu, sum, 2);
    float inv = 1.f / sum;
#pragma unroll
    for (int ji = 0; ji < 16; ++ji) ss[g][q * 16 + ji] = sj[ji];
    __syncthreads();

#pragma unroll
    for (int di = 0; di < 16; ++di) {
        int d = q * 16 + di;
        float t = 0.f;
#pragma unroll
        for (int j = 0; j < 64; ++j) t = fmaf(ss[g][j], vs[j][d], t);
        tok[g][d] = t * inv;
    }
    __syncthreads();

#pragma unroll
    for (int oi = 0; oi < 16; ++oi) {
        int o = q * 16 + oi;
        float t = 0.f;
#pragma unroll
        for (int d = 0; d < 64; ++d) t = fmaf(tok[g][d], Wos[o][d], t);
        g_ot[h * 4096 + g * 64 + o] = t;
    }
}

// ---------------------------------------------------------------------------
// prep2 (parallel): P[o][hg] = sum_d Wout[o][h*64+d] * ot[h][g][d] -> bf16
__global__ __launch_bounds__(256) void k_prep2(const float* __restrict__ Wout) {
    __shared__ float ots[64][65];
    int h = blockIdx.x, ob = blockIdx.y;
    int tid = threadIdx.x;
    for (int e = tid; e < 64 * 64; e += 256)
        ots[e >> 6][e & 63] = g_ot[h * 4096 + e];
    __syncthreads();
    int o = ob * 64 + (tid >> 2), q = tid & 3;
    float wr[64];
#pragma unroll
    for (int d = 0; d < 64; ++d) wr[d] = Wout[(size_t)o * HID + h * 64 + d];
#pragma unroll
    for (int gg = q * 16; gg < q * 16 + 16; gg += 2) {
        float s0 = 0.f, s1 = 0.f;
#pragma unroll
        for (int d = 0; d < 64; ++d) {
            s0 = fmaf(wr[d], ots[gg][d], s0);
            s1 = fmaf(wr[d], ots[gg + 1][d], s1);
        }
        g_P_bf[(size_t)o * 256 + h * 32 + (gg >> 1)] = pk(s0, s1);
    }
}

// ---------------------------------------------------------------------------
extern "C" void kernel_launch(void* const* d_in, const int* in_sizes, int n_in,
                              void* d_out, int out_size) {
    const float* x    = (const float*)d_in[0];
    const float* Wx   = (const float*)d_in[1];
    const float* bx   = (const float*)d_in[2];
    const float* Wfx  = (const float*)d_in[3];
    const float* bfx  = (const float*)d_in[4];
    const float* Ws   = (const float*)d_in[5];
    const float* bs   = (const float*)d_in[6];
    const float* temp = (const float*)d_in[7];
    const float* Wq   = (const float*)d_in[8];
    const float* Wk   = (const float*)d_in[9];
    const float* Wv   = (const float*)d_in[10];
    const float* Wo   = (const float*)d_in[11];
    const float* Wout = (const float*)d_in[12];
    const float* bout = (const float*)d_in[13];
    float* out = (float*)d_out;

    int n = in_sizes[0] / HID;
    int mtiles = (n + 127) / 128;

    uint32_t *wfxbf, *wlsbf, *wbf, *pbf, *xbf;
    float *bls;
    cudaGetSymbolAddress((void**)&wfxbf, g_Wfx_bf);
    cudaGetSymbolAddress((void**)&wlsbf, g_Wls_bf);
    cudaGetSymbolAddress((void**)&wbf, g_w_bf);
    cudaGetSymbolAddress((void**)&pbf, g_P_bf);
    cudaGetSymbolAddress((void**)&bls, g_bls);
    cudaGetSymbolAddress((void**)&xbf, g_x_bf);

    cudaFuncSetAttribute(k_gemm, cudaFuncAttributeMaxDynamicSharedMemorySize, SMEM_GEMM);
    cudaFuncSetAttribute(k_attn, cudaFuncAttributeMaxDynamicSharedMemorySize, ATTN_SMEM);

    int nqx = n * 128;   // float4 quads in x
    k_pre<<<(nqx + WFX_QUADS + 255) / 256, 256>>>(x, Wfx, nqx);

    dim3 gp1(32, NH);
    k_prep1<<<gp1, 256>>>(Wx, bx, Ws, bs, temp);

    // GEMM1 (mode 1)
    dim3 gg1(8, mtiles);
    k_gemm<<<gg1, 128, SMEM_GEMM>>>(
        (const uint16_t*)xbf, (const uint16_t*)wlsbf, (const uint16_t*)wfxbf,
        bls, bfx, 4, 1, nullptr, n);

    dim3 gpool(PBLK, NH);
    k_pool<<<gpool, 128>>>(n);

    k_attn<<<NH, 256, ATTN_SMEM>>>(Wq, Wk, Wv, Wo);

    dim3 gp2(NH, 8);
    k_prep2<<<gp2, 256>>>(Wout);

    // GEMM2 (mode 0)
    dim3 gg2(4, mtiles);
    k_gemm<<<gg2, 128, SMEM_GEMM>>>(
        (const uint16_t*)wbf, (const uint16_t*)pbf, (const uint16_t*)pbf,
        bout, bout, 4, 0, out, n);
}